// round 10
// baseline (speedup 1.0000x reference)
#include <cuda_runtime.h>
#include <cuda_bf16.h>
#include <cuda_fp8.h>
#include <cstdint>

#define ND 4096
#define NTE (ND * (size_t)ND)

// ---------------- scratch (device globals; no allocation allowed) ----------
__device__ __align__(1024) __nv_bfloat16 g_Ah[NTE];   // tril(A) hi bf16, [M,K]
__device__ __align__(1024) __nv_bfloat16 g_Bth[NTE];  // tril(B)^T hi bf16, [N,K]
__device__ __align__(1024) uint8_t g_A8h[NTE];        // e4m3(Ah)
__device__ __align__(1024) uint8_t g_A8l[NTE];        // e4m3(512*(A-Ah))
__device__ __align__(1024) uint8_t g_B8h[NTE];        // e4m3(Bh) [N,K]
__device__ __align__(1024) uint8_t g_B8l[NTE];        // e4m3(512*(Bt-Bh))

// ---------------- helpers ---------------------------------------------------
static __device__ __forceinline__ uint32_t smem_u32(const void* p) {
    return (uint32_t)__cvta_generic_to_shared(p);
}
static __device__ __forceinline__ void cp_async16(uint32_t dst, const void* src) {
    asm volatile("cp.async.cg.shared.global [%0], [%1], 16;" :: "r"(dst), "l"(src));
}
static __device__ __forceinline__ void cp_commit() {
    asm volatile("cp.async.commit_group;" ::: "memory");
}
static __device__ __forceinline__ void cp_wait2() {
    asm volatile("cp.async.wait_group 2;" ::: "memory");
}
static __device__ __forceinline__ void ldsm4(uint32_t& r0, uint32_t& r1,
                                             uint32_t& r2, uint32_t& r3, uint32_t a) {
    asm volatile("ldmatrix.sync.aligned.m8n8.x4.shared.b16 {%0,%1,%2,%3}, [%4];"
                 : "=r"(r0), "=r"(r1), "=r"(r2), "=r"(r3) : "r"(a));
}
static __device__ __forceinline__ void mma16816(float* d, const uint32_t* a,
                                                const uint32_t* b) {
    asm volatile(
        "mma.sync.aligned.m16n8k16.row.col.f32.bf16.bf16.f32 "
        "{%0,%1,%2,%3}, {%4,%5,%6,%7}, {%8,%9}, {%0,%1,%2,%3};"
        : "+f"(d[0]), "+f"(d[1]), "+f"(d[2]), "+f"(d[3])
        : "r"(a[0]), "r"(a[1]), "r"(a[2]), "r"(a[3]), "r"(b[0]), "r"(b[1]));
}
static __device__ __forceinline__ void mma16832fp8(float* d, const uint32_t* a,
                                                   const uint32_t* b) {
    asm volatile(
        "mma.sync.aligned.m16n8k32.row.col.f32.e4m3.e4m3.f32 "
        "{%0,%1,%2,%3}, {%4,%5,%6,%7}, {%8,%9}, {%0,%1,%2,%3};"
        : "+f"(d[0]), "+f"(d[1]), "+f"(d[2]), "+f"(d[3])
        : "r"(a[0]), "r"(a[1]), "r"(a[2]), "r"(a[3]), "r"(b[0]), "r"(b[1]));
}

// bf16 tile swizzle: 128 rows x 64B, 16B chunk c in 0..3
static __device__ __forceinline__ uint32_t swz(int r, int c) {
    return (uint32_t)(r * 64 + ((c ^ ((r >> 1) & 3)) << 4));
}
// fp8 tile swizzle: 128 rows x 32B (two 16B chunks h); 4 rows per 128B line,
// chunk' = (2*(r&3)+h) ^ ((r>>2)&7)  -> conflict-free ldmatrix (parity flips per line)
static __device__ __forceinline__ uint32_t swz8(int r, int h) {
    return (uint32_t)(((r >> 2) << 7) + (((((r & 3) << 1) + h) ^ ((r >> 2) & 7)) << 4));
}

static __device__ __forceinline__ uint8_t f2e4m3(float x) {
    __nv_fp8_e4m3 v(x);
    return *reinterpret_cast<uint8_t*>(&v);
}

// ---------------- pre-pass: mask + bf16/fp8 split of A (lower blocks only) --
__global__ void convert_split_A(const float* __restrict__ A) {
    size_t idx  = (size_t)blockIdx.x * blockDim.x + threadIdx.x;   // one float4
    size_t base = idx * 4;
    int i = (int)(base >> 12);     // row
    int k = (int)(base & 4095);    // col
    if ((k >> 7) > (i >> 7)) return;   // strictly-upper 128-blocks never read
    float4 v = *(const float4*)(A + base);
    float vv[4] = {v.x, v.y, v.z, v.w};
    __nv_bfloat16 h[4];
    uint32_t p8h = 0, p8l = 0;
#pragma unroll
    for (int e = 0; e < 4; ++e) {
        float x = ((k + e) <= i) ? vv[e] : 0.0f;
        __nv_bfloat16 hi = __float2bfloat16(x);
        float hf = __bfloat162float(hi);
        h[e] = hi;
        p8h |= (uint32_t)f2e4m3(hf) << (e * 8);
        p8l |= (uint32_t)f2e4m3(512.0f * (x - hf)) << (e * 8);
    }
    __nv_bfloat162* ah = (__nv_bfloat162*)(g_Ah + base);
    ah[0] = __nv_bfloat162(h[0], h[1]); ah[1] = __nv_bfloat162(h[2], h[3]);
    *(uint32_t*)(g_A8h + base) = p8h;
    *(uint32_t*)(g_A8l + base) = p8l;
}

// ---------------- pre-pass: mask + transpose + split of B (64x64 tiles) -----
__global__ void transpose_split_B(const float* __restrict__ B) {
    __shared__ float tile[64][65];
    const int bk = blockIdx.y;   // 64-wide k-tile
    const int bn = blockIdx.x;   // 64-wide n-tile
    if ((bn >> 1) > (bk >> 1)) return;   // keep only k128-block >= n128-block
    const int tx = threadIdx.x;  // 0..63
    const int ty = threadIdx.y;  // 0..3
    const int k0 = bk * 64, n0 = bn * 64;
#pragma unroll
    for (int r = ty; r < 64; r += 4) {
        int k = k0 + r, n = n0 + tx;
        float v = B[(size_t)k * ND + n];
        tile[r][tx] = (n <= k) ? v : 0.0f;
    }
    __syncthreads();
#pragma unroll
    for (int r = ty; r < 64; r += 4) {
        int n = n0 + r, k = k0 + tx;
        float x = tile[tx][r];   // = masked B[k][n]
        __nv_bfloat16 hi = __float2bfloat16(x);
        float hf = __bfloat162float(hi);
        size_t o = (size_t)n * ND + k;
        g_Bth[o] = hi;
        g_B8h[o] = f2e4m3(hf);
        g_B8l[o] = f2e4m3(512.0f * (x - hf));
    }
}

// ---------------- main GEMM ---------------------------------------------------
#define STAGES 6
// stage layout: Ah(8K) Bh(8K) A8h(4K) A8l(4K) B8h(4K) B8l(4K) = 32KB
#define O_AH   0
#define O_BH   8192
#define O_A8H  16384
#define O_A8L  20480
#define O_B8H  24576
#define O_B8L  28672
#define STAGE_BYTES 32768
#define GEMM_SMEM (STAGES * STAGE_BYTES)    // 196608

__global__ __launch_bounds__(256, 1)
void trimm_gemm(float* __restrict__ C) {
    extern __shared__ char smem[];
    const uint32_t sb = smem_u32(smem);
    const int tid = threadIdx.x;

    // ---- blocks >= 528: zero one strictly-upper 128x128 tile and exit ------
    if (blockIdx.x >= 528) {
        int uid = blockIdx.x - 528;
        int r, cum = 0;
        for (r = 0; r < 32; ++r) {
            int cnt = 31 - r;
            if (uid < cum + cnt) break;
            cum += cnt;
        }
        const int zbi = r, zbj = r + 1 + (uid - cum);
        float4* dst = (float4*)(C + (size_t)zbi * 128 * ND + zbj * 128);
        const float4 z = make_float4(0.f, 0.f, 0.f, 0.f);
#pragma unroll
        for (int it = 0; it < 16; ++it) {
            int c = it * 256 + tid;
            int row = c >> 5, q = c & 31;
            dst[(size_t)row * (ND / 4) + q] = z;
        }
        return;
    }

    const int wid = tid >> 5;
    const int lid = tid & 31;
    const int wm = wid & 1;        // 0..1 (M)
    const int wn = wid >> 1;       // 0..3 (N)

    // tile map: heaviest diagonals first
    int id = blockIdx.x;
    int dd, cum = 0;
    for (dd = 31; dd > 0; --dd) {
        int cnt = 32 - dd;
        if (id < cum + cnt) break;
        cum += cnt;
    }
    const int bj = id - cum;
    const int bi = bj + dd;

    const int kt0 = bj * 128;
    const int KT  = (bi - bj + 1) * 4;   // K=32 stages (multiple of 4)

    // bf16 cp.async coords (512 chunks per tile, 2 per thread)
    const int r0g = tid >> 2, c0g = tid & 3;
    const int r1g = (tid + 256) >> 2, c1g = tid & 3;
    // fp8 cp.async coords (256 chunks per tile, 1 per thread)
    const int r8 = tid >> 1, h8 = tid & 1;

    const int arow = bi * 128, brow = bj * 128;

    auto issue = [&](int s, int kt) {
        uint32_t st = sb + (uint32_t)s * STAGE_BYTES;
        // bf16 Ah, Bh
        cp_async16(st + O_AH + swz(r0g, c0g), g_Ah + (size_t)(arow + r0g) * ND + kt + c0g * 8);
        cp_async16(st + O_AH + swz(r1g, c1g), g_Ah + (size_t)(arow + r1g) * ND + kt + c1g * 8);
        cp_async16(st + O_BH + swz(r0g, c0g), g_Bth + (size_t)(brow + r0g) * ND + kt + c0g * 8);
        cp_async16(st + O_BH + swz(r1g, c1g), g_Bth + (size_t)(brow + r1g) * ND + kt + c1g * 8);
        // fp8 tiles
        uint32_t so8 = swz8(r8, h8);
        size_t  ga = (size_t)(arow + r8) * ND + kt + h8 * 16;
        size_t  gb = (size_t)(brow + r8) * ND + kt + h8 * 16;
        cp_async16(st + O_A8H + so8, g_A8h + ga);
        cp_async16(st + O_A8L + so8, g_A8l + ga);
        cp_async16(st + O_B8H + so8, g_B8h + gb);
        cp_async16(st + O_B8L + so8, g_B8l + gb);
    };

    float accH[4][4][4], accL[4][4][4];
#pragma unroll
    for (int a = 0; a < 4; ++a)
#pragma unroll
        for (int b = 0; b < 4; ++b)
#pragma unroll
            for (int c = 0; c < 4; ++c) { accH[a][b][c] = 0.f; accL[a][b][c] = 0.f; }

    const int g  = lid >> 3;   // 0..3
    const int rr = lid & 7;

    // one K=32 stage
    auto compute_stage = [&](int slot) {
        const uint32_t st = sb + (uint32_t)slot * STAGE_BYTES;

        // ---- bf16 hi product: 2 half-stages of K=16 ----
#pragma unroll
        for (int ks = 0; ks < 2; ++ks) {
            const int c0 = ks * 2;
            uint32_t ah[4][4], bh[4][2];
#pragma unroll
            for (int tm = 0; tm < 4; ++tm) {
                int r = wm * 64 + tm * 16 + (g & 1) * 8 + rr;
                ldsm4(ah[tm][0], ah[tm][1], ah[tm][2], ah[tm][3],
                      st + O_AH + swz(r, c0 + (g >> 1)));
            }
#pragma unroll
            for (int p = 0; p < 2; ++p) {
                int r = wn * 32 + p * 16 + (g >> 1) * 8 + rr;
                uint32_t h0, h1, h2, h3;
                ldsm4(h0, h1, h2, h3, st + O_BH + swz(r, c0 + (g & 1)));
                bh[p * 2 + 0][0] = h0; bh[p * 2 + 0][1] = h1;
                bh[p * 2 + 1][0] = h2; bh[p * 2 + 1][1] = h3;
            }
#pragma unroll
            for (int tm = 0; tm < 4; ++tm)
#pragma unroll
                for (int tn = 0; tn < 4; ++tn)
                    mma16816(accH[tm][tn], ah[tm], bh[tn]);
        }

        // ---- fp8 cross products: one K=32 step ----
        uint32_t a8h[4][4], a8l[4][4], b8h[4][2], b8l[4][2];
        {
            // A fp8: lane group g -> matrix g: row = base+(g&1)*8+rr, h = g>>1
#pragma unroll
            for (int tm = 0; tm < 4; ++tm) {
                int r = wm * 64 + tm * 16 + (g & 1) * 8 + rr;
                uint32_t off = swz8(r, g >> 1);
                ldsm4(a8h[tm][0], a8h[tm][1], a8h[tm][2], a8h[tm][3], st + O_A8H + off);
                ldsm4(a8l[tm][0], a8l[tm][1], a8l[tm][2], a8l[tm][3], st + O_A8L + off);
            }
            // B fp8: matrices (p0,h0),(p0,h1),(p1,h0),(p1,h1)
#pragma unroll
            for (int p = 0; p < 2; ++p) {
                int nt = p * 2 + (g >> 1);
                int r = wn * 32 + nt * 8 + rr;
                uint32_t off = swz8(r, g & 1);
                uint32_t h0, h1, h2, h3;
                ldsm4(h0, h1, h2, h3, st + O_B8H + off);
                b8h[p * 2 + 0][0] = h0; b8h[p * 2 + 0][1] = h1;
                b8h[p * 2 + 1][0] = h2; b8h[p * 2 + 1][1] = h3;
                ldsm4(h0, h1, h2, h3, st + O_B8L + off);
                b8l[p * 2 + 0][0] = h0; b8l[p * 2 + 0][1] = h1;
                b8l[p * 2 + 1][0] = h2; b8l[p * 2 + 1][1] = h3;
            }
        }
#pragma unroll
        for (int tm = 0; tm < 4; ++tm)
#pragma unroll
            for (int tn = 0; tn < 4; ++tn) {
                mma16832fp8(accL[tm][tn], a8l[tm], b8h[tn]);   // 512*Al . Bh
                mma16832fp8(accL[tm][tn], a8h[tm], b8l[tn]);   // Ah . 512*Bl
            }
    };

    // prologue
    issue(0, kt0);      cp_commit();
    issue(1, kt0 + 32); cp_commit();

    for (int j = 0; j < KT; j += 2) {
        if (j + 2 < KT) issue((j + 2) % STAGES, kt0 + (j + 2) * 32);
        cp_commit();
        if (j + 3 < KT) issue((j + 3) % STAGES, kt0 + (j + 3) * 32);
        cp_commit();
        cp_wait2();
        __syncthreads();
        compute_stage(j % STAGES);
        compute_stage((j + 1) % STAGES);
    }

    // epilogue: C = accH + accL/512
    const float s = 1.0f / 512.0f;
#pragma unroll
    for (int tm = 0; tm < 4; ++tm) {
#pragma unroll
        for (int tn = 0; tn < 4; ++tn) {
            int row = bi * 128 + wm * 64 + tm * 16 + (lid >> 2);
            int col = bj * 128 + wn * 32 + tn * 8 + (lid & 3) * 2;
            float2 v0 = make_float2(accH[tm][tn][0] + s * accL[tm][tn][0],
                                    accH[tm][tn][1] + s * accL[tm][tn][1]);
            float2 v1 = make_float2(accH[tm][tn][2] + s * accL[tm][tn][2],
                                    accH[tm][tn][3] + s * accL[tm][tn][3]);
            *(float2*)(C + (size_t)row * ND + col)       = v0;
            *(float2*)(C + (size_t)(row + 8) * ND + col) = v1;
        }
    }
}

// ---------------- launch ----------------------------------------------------
extern "C" void kernel_launch(void* const* d_in, const int* in_sizes, int n_in,
                              void* d_out, int out_size) {
    const float* A = (const float*)d_in[0];
    const float* B = (const float*)d_in[1];
    float* C = (float*)d_out;

    cudaFuncSetAttribute(trimm_gemm, cudaFuncAttributeMaxDynamicSharedMemorySize, GEMM_SMEM);

    convert_split_A<<<16384, 256>>>(A);
    transpose_split_B<<<dim3(64, 64), dim3(64, 4)>>>(B);
    trimm_gemm<<<1024, 256, GEMM_SMEM>>>(C);
}

// round 11
// speedup vs baseline: 1.2155x; 1.2155x over previous
#include <cuda_runtime.h>
#include <cuda_bf16.h>
#include <cstdint>

#define ND 4096
#define NTE (ND * (size_t)ND)

// ---------------- scratch (device globals; no allocation allowed) ----------
__device__ __align__(1024) __nv_bfloat16 g_Ah[NTE];   // tril(A) hi, [M,K] K-major
__device__ __align__(1024) __nv_bfloat16 g_Al[NTE];   // tril(A) lo
__device__ __align__(1024) __nv_bfloat16 g_Bth[NTE];  // tril(B)^T hi, [N,K] K-major
__device__ __align__(1024) __nv_bfloat16 g_Btl[NTE];  // tril(B)^T lo

// ---------------- helpers ---------------------------------------------------
static __device__ __forceinline__ uint32_t smem_u32(const void* p) {
    return (uint32_t)__cvta_generic_to_shared(p);
}
static __device__ __forceinline__ void cp_async16(uint32_t dst, const void* src) {
    asm volatile("cp.async.cg.shared.global [%0], [%1], 16;" :: "r"(dst), "l"(src));
}
static __device__ __forceinline__ void cp_commit() {
    asm volatile("cp.async.commit_group;" ::: "memory");
}
static __device__ __forceinline__ void cp_wait2() {
    asm volatile("cp.async.wait_group 2;" ::: "memory");
}
static __device__ __forceinline__ void ldsm4(uint32_t& r0, uint32_t& r1,
                                             uint32_t& r2, uint32_t& r3, uint32_t a) {
    asm volatile("ldmatrix.sync.aligned.m8n8.x4.shared.b16 {%0,%1,%2,%3}, [%4];"
                 : "=r"(r0), "=r"(r1), "=r"(r2), "=r"(r3) : "r"(a));
}
static __device__ __forceinline__ void mma16816(float* d, const uint32_t* a,
                                                const uint32_t* b) {
    asm volatile(
        "mma.sync.aligned.m16n8k16.row.col.f32.bf16.bf16.f32 "
        "{%0,%1,%2,%3}, {%4,%5,%6,%7}, {%8,%9}, {%0,%1,%2,%3};"
        : "+f"(d[0]), "+f"(d[1]), "+f"(d[2]), "+f"(d[3])
        : "r"(a[0]), "r"(a[1]), "r"(a[2]), "r"(a[3]), "r"(b[0]), "r"(b[1]));
}
static __device__ __forceinline__ void redadd(float* p, float v) {
    asm volatile("red.global.add.f32 [%0], %1;" :: "l"(p), "f"(v) : "memory");
}

// swizzled smem byte offset inside one 8KB tile: row r (0..127), 16B chunk c (0..3)
static __device__ __forceinline__ uint32_t swz(int r, int c) {
    return (uint32_t)(r * 64 + ((c ^ ((r >> 1) & 3)) << 4));
}

// ---------------- pre-pass: mask + bf16 hi/lo split of A (lower blocks only) -
__global__ void convert_split_A(const float* __restrict__ A) {
    size_t idx  = (size_t)blockIdx.x * blockDim.x + threadIdx.x;   // one float4
    size_t base = idx * 4;
    int i = (int)(base >> 12);     // row
    int k = (int)(base & 4095);    // col
    if ((k >> 7) > (i >> 7)) return;   // strictly-upper 128-blocks never read
    float4 v = *(const float4*)(A + base);
    float vv[4] = {v.x, v.y, v.z, v.w};
    __nv_bfloat16 h[4], l[4];
#pragma unroll
    for (int e = 0; e < 4; ++e) {
        float x = ((k + e) <= i) ? vv[e] : 0.0f;
        __nv_bfloat16 hi = __float2bfloat16(x);
        float res = x - __bfloat162float(hi);
        h[e] = hi;
        l[e] = __float2bfloat16(res);
    }
    __nv_bfloat162* ah = (__nv_bfloat162*)(g_Ah + base);
    __nv_bfloat162* al = (__nv_bfloat162*)(g_Al + base);
    ah[0] = __nv_bfloat162(h[0], h[1]); ah[1] = __nv_bfloat162(h[2], h[3]);
    al[0] = __nv_bfloat162(l[0], l[1]); al[1] = __nv_bfloat162(l[2], l[3]);
}

// ---------------- pre-pass: mask + transpose + split of B (64x64 tiles) -----
__global__ void transpose_split_B(const float* __restrict__ B) {
    __shared__ float tile[64][65];
    const int bk = blockIdx.y;
    const int bn = blockIdx.x;
    if ((bn >> 1) > (bk >> 1)) return;   // keep only k128-block >= n128-block
    const int tx = threadIdx.x;  // 0..63
    const int ty = threadIdx.y;  // 0..3
    const int k0 = bk * 64, n0 = bn * 64;
#pragma unroll
    for (int r = ty; r < 64; r += 4) {
        int k = k0 + r, n = n0 + tx;
        float v = B[(size_t)k * ND + n];
        tile[r][tx] = (n <= k) ? v : 0.0f;
    }
    __syncthreads();
#pragma unroll
    for (int r = ty; r < 64; r += 4) {
        int n = n0 + r, k = k0 + tx;
        float x = tile[tx][r];   // = masked B[k][n]
        __nv_bfloat16 hi = __float2bfloat16(x);
        float res = x - __bfloat162float(hi);
        g_Bth[(size_t)n * ND + k] = hi;
        g_Btl[(size_t)n * ND + k] = __float2bfloat16(res);
    }
}

// ---------------- zero the whole output -------------------------------------
__global__ void zero_out(float4* __restrict__ C) {
    size_t i = (size_t)blockIdx.x * blockDim.x + threadIdx.x;
    C[i] = make_float4(0.f, 0.f, 0.f, 0.f);
}

// ---------------- main GEMM: split-K over K=1024 chunks ---------------------
#define STAGES 6
#define TILE_BYTES 8192                     // one 128x32 bf16 tile
#define STAGE_BYTES (4 * TILE_BYTES)        // Ah, Al, Bh, Bl
#define GEMM_SMEM (STAGES * STAGE_BYTES)    // 196608
#define CH 32                               // K-stages per chunk (K=1024)
// work units = sum_d (32-d)*ceil((d+1)*4/CH) = 1000
#define UNITS 1000

__global__ __launch_bounds__(256, 1)
void trimm_gemm(float* __restrict__ C) {
    extern __shared__ char smem[];
    const uint32_t sb = smem_u32(smem);
    const int tid = threadIdx.x;
    const int wid = tid >> 5;
    const int lid = tid & 31;
    const int wm = wid & 1;        // 0..1 (M)
    const int wn = wid >> 1;       // 0..3 (N)

    // ---- work-unit map: heaviest diagonals first, chunks within tile -------
    int id = blockIdx.x;
    int d, cum = 0, nch = 1;
    for (d = 31; d >= 0; --d) {
        nch = ((d + 1) * 4 + CH - 1) / CH;
        int cnt = (32 - d) * nch;
        if (id < cum + cnt) break;
        cum += cnt;
    }
    const int rem = id - cum;
    const int bj  = rem / nch;
    const int cch = rem % nch;
    const int bi  = bj + d;

    const int KTtile = (d + 1) * 4;            // total K=32 stages of the tile
    const int ks0    = cch * CH;               // first stage of this chunk
    const int KTc    = min(CH, KTtile - ks0);  // stages in this chunk (even, >=4)
    const int kt0    = bj * 128 + ks0 * 32;    // element offset of chunk start

    // per-thread cp.async chunk coords: two chunks per 8KB tile
    const int r0g = tid >> 2, c0g = tid & 3;
    const int r1g = (tid + 256) >> 2, c1g = tid & 3;

    const __nv_bfloat16* srcs[4] = {g_Ah, g_Al, g_Bth, g_Btl};
    const int rowbase[4] = {bi * 128, bi * 128, bj * 128, bj * 128};

    auto issue = [&](int s, int kt) {
        uint32_t stage_base = sb + (uint32_t)s * STAGE_BYTES;
#pragma unroll
        for (int a = 0; a < 4; ++a) {
            const __nv_bfloat16* src = srcs[a];
            uint32_t tb = stage_base + a * TILE_BYTES;
            cp_async16(tb + swz(r0g, c0g),
                       src + (size_t)(rowbase[a] + r0g) * ND + kt + c0g * 8);
            cp_async16(tb + swz(r1g, c1g),
                       src + (size_t)(rowbase[a] + r1g) * ND + kt + c1g * 8);
        }
    };

    float acc[4][4][4];
#pragma unroll
    for (int a = 0; a < 4; ++a)
#pragma unroll
        for (int b = 0; b < 4; ++b)
#pragma unroll
            for (int c = 0; c < 4; ++c) acc[a][b][c] = 0.f;

    const int g  = lid >> 3;
    const int rr = lid & 7;

    auto compute_stage = [&](int slot) {
        const uint32_t stage = sb + (uint32_t)slot * STAGE_BYTES;
        const uint32_t aH = stage;
        const uint32_t bH = stage + 2 * TILE_BYTES;
#pragma unroll
        for (int ks = 0; ks < 2; ++ks) {
            const int c0 = ks * 2;
            uint32_t ah[4][4], al[4][4], bh[4][2], bl[4][2];
#pragma unroll
            for (int tm = 0; tm < 4; ++tm) {
                int r = wm * 64 + tm * 16 + (g & 1) * 8 + rr;
                uint32_t off = swz(r, c0 + (g >> 1));
                ldsm4(ah[tm][0], ah[tm][1], ah[tm][2], ah[tm][3], aH + off);
                ldsm4(al[tm][0], al[tm][1], al[tm][2], al[tm][3], aH + TILE_BYTES + off);
            }
#pragma unroll
            for (int p = 0; p < 2; ++p) {
                int r = wn * 32 + p * 16 + (g >> 1) * 8 + rr;
                uint32_t off = swz(r, c0 + (g & 1));
                uint32_t h0, h1, h2, h3;
                ldsm4(h0, h1, h2, h3, bH + off);
                bh[p * 2 + 0][0] = h0; bh[p * 2 + 0][1] = h1;
                bh[p * 2 + 1][0] = h2; bh[p * 2 + 1][1] = h3;
                ldsm4(h0, h1, h2, h3, bH + TILE_BYTES + off);
                bl[p * 2 + 0][0] = h0; bl[p * 2 + 0][1] = h1;
                bl[p * 2 + 1][0] = h2; bl[p * 2 + 1][1] = h3;
            }
#pragma unroll
            for (int tm = 0; tm < 4; ++tm)
#pragma unroll
                for (int tn = 0; tn < 4; ++tn) {
                    mma16816(acc[tm][tn], ah[tm], bh[tn]);
                    mma16816(acc[tm][tn], ah[tm], bl[tn]);
                    mma16816(acc[tm][tn], al[tm], bh[tn]);
                }
        }
    };

    // prologue: stages 0,1 (KTc >= 4 always)
    issue(0, kt0);      cp_commit();
    issue(1, kt0 + 32); cp_commit();

    // main loop: two K=32 stages per barrier.
    // commits after iter-j = j+4 -> wait_group 2 completes stages <= j+1.
    // slot reuse: writes {j+2,j+3} vs laggard reads {j-2,j-1} mod 6 -> safe.
    for (int j = 0; j < KTc; j += 2) {
        if (j + 2 < KTc) issue((j + 2) % STAGES, kt0 + (j + 2) * 32);
        cp_commit();
        if (j + 3 < KTc) issue((j + 3) % STAGES, kt0 + (j + 3) * 32);
        cp_commit();
        cp_wait2();
        __syncthreads();
        compute_stage(j % STAGES);
        compute_stage((j + 1) % STAGES);
    }

    // epilogue: single-chunk tiles store, multi-chunk tiles atomically add
    if (nch == 1) {
#pragma unroll
        for (int tm = 0; tm < 4; ++tm)
#pragma unroll
            for (int tn = 0; tn < 4; ++tn) {
                int row = bi * 128 + wm * 64 + tm * 16 + (lid >> 2);
                int col = bj * 128 + wn * 32 + tn * 8 + (lid & 3) * 2;
                float2 v0 = make_float2(acc[tm][tn][0], acc[tm][tn][1]);
                float2 v1 = make_float2(acc[tm][tn][2], acc[tm][tn][3]);
                *(float2*)(C + (size_t)row * ND + col)       = v0;
                *(float2*)(C + (size_t)(row + 8) * ND + col) = v1;
            }
    } else {
#pragma unroll
        for (int tm = 0; tm < 4; ++tm)
#pragma unroll
            for (int tn = 0; tn < 4; ++tn) {
                int row = bi * 128 + wm * 64 + tm * 16 + (lid >> 2);
                int col = bj * 128 + wn * 32 + tn * 8 + (lid & 3) * 2;
                float* p0 = C + (size_t)row * ND + col;
                float* p1 = C + (size_t)(row + 8) * ND + col;
                redadd(p0,     acc[tm][tn][0]);
                redadd(p0 + 1, acc[tm][tn][1]);
                redadd(p1,     acc[tm][tn][2]);
                redadd(p1 + 1, acc[tm][tn][3]);
            }
    }
}

// ---------------- launch ----------------------------------------------------
extern "C" void kernel_launch(void* const* d_in, const int* in_sizes, int n_in,
                              void* d_out, int out_size) {
    const float* A = (const float*)d_in[0];
    const float* B = (const float*)d_in[1];
    float* C = (float*)d_out;

    cudaFuncSetAttribute(trimm_gemm, cudaFuncAttributeMaxDynamicSharedMemorySize, GEMM_SMEM);

    convert_split_A<<<16384, 256>>>(A);
    transpose_split_B<<<dim3(64, 64), dim3(64, 4)>>>(B);
    zero_out<<<16384, 256>>>((float4*)C);
    trimm_gemm<<<UNITS, 256, GEMM_SMEM>>>(C);
}